// round 2
// baseline (speedup 1.0000x reference)
#include <cuda_runtime.h>
#include <cstdint>

#define T_ 512
#define F_ 24
#define H_ 12

typedef unsigned long long u64;

// ---- f32x2 packed helpers (sm_103a) ----
__device__ __forceinline__ u64 pk2(float lo, float hi) {
    u64 r; asm("mov.b64 %0,{%1,%2};" : "=l"(r) : "f"(lo), "f"(hi)); return r;
}
__device__ __forceinline__ u64 dup2(float v) {
    u64 r; asm("mov.b64 %0,{%1,%1};" : "=l"(r) : "f"(v)); return r;
}
__device__ __forceinline__ void fma2(u64 &d, u64 a, u64 b) {
    asm("fma.rn.f32x2 %0,%1,%2,%0;" : "+l"(d) : "l"(a), "l"(b));
}
__device__ __forceinline__ u64 add2(u64 a, u64 b) {
    u64 r; asm("add.rn.f32x2 %0,%1,%2;" : "=l"(r) : "l"(a), "l"(b)); return r;
}
__device__ __forceinline__ void unpk2(u64 v, float &lo, float &hi) {
    asm("mov.b64 {%0,%1},%2;" : "=f"(lo), "=f"(hi) : "l"(v));
}

// tanh(x) = 1 - 2/(2^(x*2log2e) + 1): FMUL + EX2 + FADD + RCP + FFMA
// (3 fma-pipe ops, 2 MUFU; saturates correctly at +/-1; err ~1e-7)
__device__ __forceinline__ float fast_tanh(float x) {
    float g = x * 2.885390081777927f;   // 2*log2(e)
    float e; asm("ex2.approx.f32 %0, %1;" : "=f"(e) : "f"(g));
    float d = e + 1.0f;
    float r; asm("rcp.approx.f32 %0, %1;" : "=f"(r) : "f"(d));
    return fmaf(-2.0f, r, 1.0f);
}

// 4 threads per batch element; lane%4 = 2*ph + pf
//   ph: which 6 hidden units (packed as 3 f32x2 h-pairs)
//   pf: which input/recurrent half is summed (f in [12pf,..), k in [6pf,..))
// Software-pipelined: step t+1's input projection issues between the
// reduction shfls of step t and their consumption, hiding shfl+tanh latency.
__global__ void __launch_bounds__(128, 2)
rnn_fused_kernel(const float* __restrict__ x,
                 const float* __restrict__ W_ih, const float* __restrict__ b_ih,
                 const float* __restrict__ W_hh, const float* __restrict__ b_hh,
                 const float* __restrict__ W1,  const float* __restrict__ b1,
                 const float* __restrict__ W2,  const float* __restrict__ b2,
                 const float* __restrict__ W3,  const float* __restrict__ b3,
                 float* __restrict__ out)
{
    const int tid  = blockIdx.x * blockDim.x + threadIdx.x;
    const int elem = tid >> 2;
    const int lane = threadIdx.x & 31;
    const int pf   = lane & 1;
    const int ph   = (lane >> 1) & 1;
    const int h0   = ph * 6;
    const int f0   = pf * 12;
    const int k0   = pf * 6;
    const unsigned FULL = 0xFFFFFFFFu;

    // ---- weights in registers, packed along h-pairs ----
    u64 Wihp[3][12];
    u64 Whhp[3][6];
    u64 binit[3];
    #pragma unroll
    for (int hp = 0; hp < 3; hp++) {
        const int ha = h0 + 2 * hp, hb = ha + 1;
        #pragma unroll
        for (int f = 0; f < 12; f++)
            Wihp[hp][f] = pk2(W_ih[ha * F_ + f0 + f], W_ih[hb * F_ + f0 + f]);
        #pragma unroll
        for (int k = 0; k < 6; k++)
            Whhp[hp][k] = pk2(W_hh[ha * H_ + k0 + k], W_hh[hb * H_ + k0 + k]);
        binit[hp] = pf ? 0ULL
                       : pk2(b_ih[ha] + b_hh[ha], b_ih[hb] + b_hh[hb]);
    }

    const float* xb = x + (size_t)elem * (T_ * F_) + f0;

    // ---- prologue: input projection for t=0, prefetch x[1] ----
    u64 ai0 = binit[0], ai1 = binit[1], ai2 = binit[2];
    {
        float4 c0 = __ldcs((const float4*)(xb + 0));
        float4 c1 = __ldcs((const float4*)(xb + 4));
        float4 c2 = __ldcs((const float4*)(xb + 8));
        const float xs[12] = {c0.x,c0.y,c0.z,c0.w, c1.x,c1.y,c1.z,c1.w,
                              c2.x,c2.y,c2.z,c2.w};
        #pragma unroll
        for (int f = 0; f < 12; f++) {
            u64 xd = dup2(xs[f]);
            fma2(ai0, Wihp[0][f], xd);
            fma2(ai1, Wihp[1][f], xd);
            fma2(ai2, Wihp[2][f], xd);
        }
    }
    float4 n0 = __ldcs((const float4*)(xb + F_ + 0));
    float4 n1 = __ldcs((const float4*)(xb + F_ + 4));
    float4 n2 = __ldcs((const float4*)(xb + F_ + 8));

    float h[6];
    #pragma unroll
    for (int i = 0; i < 6; i++) h[i] = 0.0f;
    float th0, th1, th2, th3, th4, th5;

    const int bcsrc = (lane & ~3) | (pf << 1);

    for (int t = 0; t < T_; t++) {
        // (1) recurrent partials for step t (depends on h_{t-1})
        #pragma unroll
        for (int k = 0; k < 6; k++) {
            u64 hd = dup2(h[k]);
            fma2(ai0, Whhp[0][k], hd);
            fma2(ai1, Whhp[1][k], hd);
            fma2(ai2, Whhp[2][k], hd);
        }

        // (2) issue cross-lane reduction (f-partner lane^1)
        u64 p0 = __shfl_xor_sync(FULL, ai0, 1);
        u64 p1 = __shfl_xor_sync(FULL, ai1, 1);
        u64 p2 = __shfl_xor_sync(FULL, ai2, 1);

        // (3) independent work: input projection for step t+1 + prefetch t+2
        u64 an0 = binit[0], an1 = binit[1], an2 = binit[2];
        {
            const float xs[12] = {n0.x,n0.y,n0.z,n0.w, n1.x,n1.y,n1.z,n1.w,
                                  n2.x,n2.y,n2.z,n2.w};
            #pragma unroll
            for (int f = 0; f < 12; f++) {
                u64 xd = dup2(xs[f]);
                fma2(an0, Wihp[0][f], xd);
                fma2(an1, Wihp[1][f], xd);
                fma2(an2, Wihp[2][f], xd);
            }
        }
        const int tn = (t < T_ - 2) ? t + 2 : T_ - 1;
        const float* xp = xb + (size_t)tn * F_;
        n0 = __ldcs((const float4*)(xp + 0));
        n1 = __ldcs((const float4*)(xp + 4));
        n2 = __ldcs((const float4*)(xp + 8));

        // (4) finish step t: packed add, tanh, broadcast
        u64 s0 = add2(ai0, p0);
        u64 s1 = add2(ai1, p1);
        u64 s2 = add2(ai2, p2);
        float a0, a1, a2, a3, a4, a5;
        unpk2(s0, a0, a1);
        unpk2(s1, a2, a3);
        unpk2(s2, a4, a5);
        th0 = fast_tanh(a0);
        th1 = fast_tanh(a1);
        th2 = fast_tanh(a2);
        th3 = fast_tanh(a3);
        th4 = fast_tanh(a4);
        th5 = fast_tanh(a5);

        h[0] = __shfl_sync(FULL, th0, bcsrc);
        h[1] = __shfl_sync(FULL, th1, bcsrc);
        h[2] = __shfl_sync(FULL, th2, bcsrc);
        h[3] = __shfl_sync(FULL, th3, bcsrc);
        h[4] = __shfl_sync(FULL, th4, bcsrc);
        h[5] = __shfl_sync(FULL, th5, bcsrc);

        ai0 = an0; ai1 = an1; ai2 = an2;
    }

    // ---- gather full h_T, run the tiny MLP head ----
    const int base = lane & ~3;
    float hf[12];
    hf[0]  = __shfl_sync(FULL, th0, base);
    hf[1]  = __shfl_sync(FULL, th1, base);
    hf[2]  = __shfl_sync(FULL, th2, base);
    hf[3]  = __shfl_sync(FULL, th3, base);
    hf[4]  = __shfl_sync(FULL, th4, base);
    hf[5]  = __shfl_sync(FULL, th5, base);
    hf[6]  = __shfl_sync(FULL, th0, base + 2);
    hf[7]  = __shfl_sync(FULL, th1, base + 2);
    hf[8]  = __shfl_sync(FULL, th2, base + 2);
    hf[9]  = __shfl_sync(FULL, th3, base + 2);
    hf[10] = __shfl_sync(FULL, th4, base + 2);
    hf[11] = __shfl_sync(FULL, th5, base + 2);

    if ((lane & 3) == 0) {
        float o1[12];
        #pragma unroll
        for (int i = 0; i < 12; i++) {
            float s = b1[i];
            #pragma unroll
            for (int j = 0; j < 12; j++) s = fmaf(W1[i * 12 + j], hf[j], s);
            o1[i] = fmaxf(s, 0.0f);
        }
        float o2[12];
        #pragma unroll
        for (int i = 0; i < 12; i++) {
            float s = b2[i];
            #pragma unroll
            for (int j = 0; j < 12; j++) s = fmaf(W2[i * 12 + j], o1[j], s);
            o2[i] = fmaxf(s, 0.0f);
        }
        float s = b3[0];
        #pragma unroll
        for (int j = 0; j < 12; j++) s = fmaf(W3[j], o2[j], s);
        out[elem] = s;
    }
}

extern "C" void kernel_launch(void* const* d_in, const int* in_sizes, int n_in,
                              void* d_out, int out_size)
{
    (void)in_sizes; (void)n_in; (void)out_size;
    const float* x    = (const float*)d_in[0];
    const float* W_ih = (const float*)d_in[1];
    const float* b_ih = (const float*)d_in[2];
    const float* W_hh = (const float*)d_in[3];
    const float* b_hh = (const float*)d_in[4];
    const float* W1   = (const float*)d_in[5];
    const float* b1   = (const float*)d_in[6];
    const float* W2   = (const float*)d_in[7];
    const float* b2   = (const float*)d_in[8];
    const float* W3   = (const float*)d_in[9];
    const float* b3   = (const float*)d_in[10];
    float* out = (float*)d_out;

    rnn_fused_kernel<<<256, 128>>>(x, W_ih, b_ih, W_hh, b_hh,
                                   W1, b1, W2, b2, W3, b3, out);
}

// round 3
// speedup vs baseline: 1.2763x; 1.2763x over previous
#include <cuda_runtime.h>
#include <cstdint>

#define T_ 512
#define F_ 24
#define H_ 12

typedef unsigned long long u64;

// ---- f32x2 packed helpers (sm_103a) ----
__device__ __forceinline__ u64 pk2(float lo, float hi) {
    u64 r; asm("mov.b64 %0,{%1,%2};" : "=l"(r) : "f"(lo), "f"(hi)); return r;
}
__device__ __forceinline__ u64 dup2(float v) {
    u64 r; asm("mov.b64 %0,{%1,%1};" : "=l"(r) : "f"(v)); return r;
}
__device__ __forceinline__ void fma2(u64 &d, u64 a, u64 b) {
    asm("fma.rn.f32x2 %0,%1,%2,%0;" : "+l"(d) : "l"(a), "l"(b));
}
__device__ __forceinline__ u64 add2(u64 a, u64 b) {
    u64 r; asm("add.rn.f32x2 %0,%1,%2;" : "=l"(r) : "l"(a), "l"(b)); return r;
}
__device__ __forceinline__ void unpk2(u64 v, float &lo, float &hi) {
    asm("mov.b64 {%0,%1},%2;" : "=f"(lo), "=f"(hi) : "l"(v));
}

// tanh(x) = 1 - 2/(2^(2x*log2e)+1): FMUL + EX2 + FADD + RCP + FFMA (err ~1e-7)
__device__ __forceinline__ float fast_tanh(float x) {
    float g = x * 2.885390081777927f;   // 2*log2(e)
    float e; asm("ex2.approx.f32 %0, %1;" : "=f"(e) : "f"(g));
    float d = e + 1.0f;
    float r; asm("rcp.approx.f32 %0, %1;" : "=f"(r) : "f"(d));
    return fmaf(-2.0f, r, 1.0f);
}

// 8 threads per batch element: id = lane&7, pf = id&3 (f-quarter, 6 f; also
// k-slice of 3 for the recurrence), ph = id>>2 (h-half, 6 h as 3 f32x2 pairs).
// Reduction: butterfly xor1 (packed u64) then xor2 on only the 3 values this
// lane finalizes; tanh split across pf-parity (3 per thread).
__global__ void __launch_bounds__(128, 4)
rnn_fused_kernel(const float* __restrict__ x,
                 const float* __restrict__ W_ih, const float* __restrict__ b_ih,
                 const float* __restrict__ W_hh, const float* __restrict__ b_hh,
                 const float* __restrict__ W1,  const float* __restrict__ b1,
                 const float* __restrict__ W2,  const float* __restrict__ b2,
                 const float* __restrict__ W3,  const float* __restrict__ b3,
                 float* __restrict__ out)
{
    const int tid  = blockIdx.x * blockDim.x + threadIdx.x;
    const int elem = tid >> 3;
    const int lane = threadIdx.x & 31;
    const int id   = lane & 7;
    const int pf   = id & 3;
    const int ph   = id >> 2;
    const int par  = pf & 1;          // tanh-parity
    const int h0   = ph * 6;
    const int f0   = pf * 6;
    const int k0   = pf * 3;
    const unsigned FULL = 0xFFFFFFFFu;

    // ---- weights in registers (packed along h-pairs) ----
    u64 Wihp[3][6];
    u64 Whhp[3][3];
    u64 binit[3];
    #pragma unroll
    for (int hp = 0; hp < 3; hp++) {
        const int ha = h0 + 2 * hp, hb = ha + 1;
        #pragma unroll
        for (int f = 0; f < 6; f++)
            Wihp[hp][f] = pk2(W_ih[ha * F_ + f0 + f], W_ih[hb * F_ + f0 + f]);
        #pragma unroll
        for (int k = 0; k < 3; k++)
            Whhp[hp][k] = pk2(W_hh[ha * H_ + k0 + k], W_hh[hb * H_ + k0 + k]);
        binit[hp] = (pf == 0) ? pk2(b_ih[ha] + b_hh[ha], b_ih[hb] + b_hh[hb])
                              : 0ULL;
    }

    const float* xb = x + (size_t)elem * (T_ * F_) + f0;

    // current-step x: 6 floats = 3 float2 (8B aligned)
    float2 xc0 = *(const float2*)(xb + 0);
    float2 xc1 = *(const float2*)(xb + 2);
    float2 xc2 = *(const float2*)(xb + 4);

    float h[3];                 // h[k0 .. k0+3) — my recurrence slice
    h[0] = h[1] = h[2] = 0.0f;
    float t0 = 0.f, t1 = 0.f, t2 = 0.f;   // my 3 finalized h values

    // broadcast source for my slice j=pf: owner lane with ph=(pf>>1), parity=(pf&1)
    const int bcsrc = (lane & ~7) | ((pf >> 1) << 2) | par;

    #pragma unroll 2
    for (int t = 0; t < T_; t++) {
        // input projection for step t (h-independent; overlappable across iters)
        u64 a0 = binit[0], a1 = binit[1], a2 = binit[2];
        const float xs[6] = {xc0.x, xc0.y, xc1.x, xc1.y, xc2.x, xc2.y};
        #pragma unroll
        for (int f = 0; f < 6; f++) {
            u64 xd = dup2(xs[f]);
            fma2(a0, Wihp[0][f], xd);
            fma2(a1, Wihp[1][f], xd);
            fma2(a2, Wihp[2][f], xd);
        }

        // prefetch next step's x
        if (t < T_ - 1) {
            const float* xn = xb + (size_t)(t + 1) * F_;
            xc0 = *(const float2*)(xn + 0);
            xc1 = *(const float2*)(xn + 2);
            xc2 = *(const float2*)(xn + 4);
        }

        // recurrent partials (my 3 k's)
        #pragma unroll
        for (int k = 0; k < 3; k++) {
            u64 hd = dup2(h[k]);
            fma2(a0, Whhp[0][k], hd);
            fma2(a1, Whhp[1][k], hd);
            fma2(a2, Whhp[2][k], hd);
        }

        // butterfly round 1 (xor1), packed
        a0 = add2(a0, __shfl_xor_sync(FULL, a0, 1));
        a1 = add2(a1, __shfl_xor_sync(FULL, a1, 1));
        a2 = add2(a2, __shfl_xor_sync(FULL, a2, 1));

        float p0, p1, p2, p3, p4, p5;
        unpk2(a0, p0, p1);
        unpk2(a1, p2, p3);
        unpk2(a2, p4, p5);

        // round 2 (xor2): only the 3 values this lane finalizes
        float v0 = par ? p3 : p0;
        float v1 = par ? p4 : p1;
        float v2 = par ? p5 : p2;
        v0 += __shfl_xor_sync(FULL, v0, 2);
        v1 += __shfl_xor_sync(FULL, v1, 2);
        v2 += __shfl_xor_sync(FULL, v2, 2);

        t0 = fast_tanh(v0);      // = h[6*ph + 3*par + 0..2]
        t1 = fast_tanh(v1);
        t2 = fast_tanh(v2);

        // fetch my recurrence slice h[k0..k0+3)
        h[0] = __shfl_sync(FULL, t0, bcsrc);
        h[1] = __shfl_sync(FULL, t1, bcsrc);
        h[2] = __shfl_sync(FULL, t2, bcsrc);
    }

    // ---- gather full h_T (slices: id0->h[0:3), id1->h[3:6), id4->h[6:9), id5->h[9:12)) ----
    const int base = lane & ~7;
    float hf[12];
    hf[0]  = __shfl_sync(FULL, t0, base + 0);
    hf[1]  = __shfl_sync(FULL, t1, base + 0);
    hf[2]  = __shfl_sync(FULL, t2, base + 0);
    hf[3]  = __shfl_sync(FULL, t0, base + 1);
    hf[4]  = __shfl_sync(FULL, t1, base + 1);
    hf[5]  = __shfl_sync(FULL, t2, base + 1);
    hf[6]  = __shfl_sync(FULL, t0, base + 4);
    hf[7]  = __shfl_sync(FULL, t1, base + 4);
    hf[8]  = __shfl_sync(FULL, t2, base + 4);
    hf[9]  = __shfl_sync(FULL, t0, base + 5);
    hf[10] = __shfl_sync(FULL, t1, base + 5);
    hf[11] = __shfl_sync(FULL, t2, base + 5);

    if (id == 0) {
        float o1[12];
        #pragma unroll
        for (int i = 0; i < 12; i++) {
            float s = b1[i];
            #pragma unroll
            for (int j = 0; j < 12; j++) s = fmaf(W1[i * 12 + j], hf[j], s);
            o1[i] = fmaxf(s, 0.0f);
        }
        float o2[12];
        #pragma unroll
        for (int i = 0; i < 12; i++) {
            float s = b2[i];
            #pragma unroll
            for (int j = 0; j < 12; j++) s = fmaf(W2[i * 12 + j], o1[j], s);
            o2[i] = fmaxf(s, 0.0f);
        }
        float s = b3[0];
        #pragma unroll
        for (int j = 0; j < 12; j++) s = fmaf(W3[j], o2[j], s);
        out[elem] = s;
    }
}

extern "C" void kernel_launch(void* const* d_in, const int* in_sizes, int n_in,
                              void* d_out, int out_size)
{
    (void)in_sizes; (void)n_in; (void)out_size;
    const float* x    = (const float*)d_in[0];
    const float* W_ih = (const float*)d_in[1];
    const float* b_ih = (const float*)d_in[2];
    const float* W_hh = (const float*)d_in[3];
    const float* b_hh = (const float*)d_in[4];
    const float* W1   = (const float*)d_in[5];
    const float* b1   = (const float*)d_in[6];
    const float* W2   = (const float*)d_in[7];
    const float* b2   = (const float*)d_in[8];
    const float* W3   = (const float*)d_in[9];
    const float* b3   = (const float*)d_in[10];
    float* out = (float*)d_out;

    // 8 threads/element * 8192 elements = 65536 threads
    rnn_fused_kernel<<<512, 128>>>(x, W_ih, b_ih, W_hh, b_hh,
                                   W1, b1, W2, b2, W3, b3, out);
}